// round 9
// baseline (speedup 1.0000x reference)
#include <cuda_runtime.h>
#include <cuda_bf16.h>
#include <math.h>
#include <cstdint>

#define BB 32
#define NN 512
#define FF 1024
#define HH 8
#define DD 128

// ---------------------------------------------------------------------------
// Device scratch (allocation-free), single bf16 plane each
__device__ unsigned short g_x1h[BB * NN * FF];
__device__ unsigned short g_kgh[BB * NN * FF];
__device__ unsigned short g_qgh[BB * NN * FF];
__device__ unsigned short g_vth[BB * NN * FF];
__device__ unsigned short g_vbh[BB * NN * FF];
__device__ unsigned short g_wqth[FF * FF];
__device__ unsigned short g_wlth[FF * FF];
__device__ unsigned short g_atth[(size_t)BB * HH * NN * NN];
__device__ float g_gate[BB * FF];

__device__ __forceinline__ unsigned short f2bf(float v) {
    __nv_bfloat16 h = __float2bfloat16(v);
    return *reinterpret_cast<unsigned short*>(&h);
}
// packed: lo 16 bits = bf16(v0), hi = bf16(v1)
__device__ __forceinline__ uint32_t pack_bf2(float v0, float v1) {
    uint32_t r;
    asm("cvt.rn.bf16x2.f32 %0, %1, %2;" : "=r"(r) : "f"(v1), "f"(v0));
    return r;
}

__device__ __forceinline__ uint32_t smem_u32(const void* p) {
    uint32_t a;
    asm("{ .reg .u64 t; cvta.to.shared.u64 t, %1; cvt.u32.u64 %0, t; }" : "=r"(a) : "l"(p));
    return a;
}
__device__ __forceinline__ void cpa16(uint32_t dst, const void* src) {
    asm volatile("cp.async.cg.shared.global [%0], [%1], 16;" :: "r"(dst), "l"(src));
}
#define CP_COMMIT() asm volatile("cp.async.commit_group;" ::: "memory")
#define CP_WAIT(n) asm volatile("cp.async.wait_group %0;" :: "n"(n) : "memory")

__device__ __forceinline__ void ldsm4(uint32_t* r, uint32_t addr) {
    asm volatile("ldmatrix.sync.aligned.m8n8.x4.shared.b16 {%0,%1,%2,%3}, [%4];"
                 : "=r"(r[0]), "=r"(r[1]), "=r"(r[2]), "=r"(r[3]) : "r"(addr));
}
__device__ __forceinline__ void mma_bf16(float* d, const uint32_t* a, const uint32_t* b) {
    asm volatile(
        "mma.sync.aligned.m16n8k16.row.col.f32.bf16.bf16.f32 "
        "{%0,%1,%2,%3}, {%4,%5,%6,%7}, {%8,%9}, {%0,%1,%2,%3};"
        : "+f"(d[0]), "+f"(d[1]), "+f"(d[2]), "+f"(d[3])
        : "r"(a[0]), "r"(a[1]), "r"(a[2]), "r"(a[3]), "r"(b[0]), "r"(b[1]));
}

// ---------------------------------------------------------------------------
// Small kernels
__global__ void gate_kernel(const float* __restrict__ x2, float* __restrict__ gate) {
    int b = blockIdx.x;
    int f = threadIdx.x;
    const float* p = x2 + (size_t)b * NN * FF + f;
    float s = 0.f;
#pragma unroll 8
    for (int n = 0; n < NN; n++) s += p[(size_t)n * FF];
    gate[b * FF + f] = s * (1.0f / NN);
}

__global__ void conv_x1(const float* __restrict__ x1, const float* __restrict__ gate,
                        unsigned short* xh, unsigned short* kh) {
    size_t i = (size_t)blockIdx.x * 256 + threadIdx.x;
    int c = (int)(i & (FF - 1));
    int b = (int)(i >> 19);
    float v = x1[i];
    xh[i] = f2bf(v);
    kh[i] = f2bf(v * gate[b * FF + c]);
}

// Wqt[h*128+d][f] = Wq[h][f][d]  (tiled transpose)
__global__ void conv_wq(const float* __restrict__ W, unsigned short* __restrict__ o) {
    __shared__ float s[32][33];
    int h = blockIdx.z;
    int f0 = blockIdx.x * 32, d0 = blockIdx.y * 32;
    int tx = threadIdx.x, ty = threadIdx.y;
#pragma unroll
    for (int i = 0; i < 32; i += 8)
        s[ty + i][tx] = W[((size_t)h * FF + f0 + ty + i) * DD + d0 + tx];
    __syncthreads();
#pragma unroll
    for (int i = 0; i < 32; i += 8)
        o[(size_t)(h * DD + d0 + ty + i) * FF + f0 + tx] = f2bf(s[tx][ty + i]);
}

// Wlt[n][k] = Wl[k][n]  (tiled transpose)
__global__ void conv_wl(const float* __restrict__ W, unsigned short* __restrict__ o) {
    __shared__ float s[32][33];
    int k0 = blockIdx.x * 32, n0 = blockIdx.y * 32;
    int tx = threadIdx.x, ty = threadIdx.y;
#pragma unroll
    for (int i = 0; i < 32; i += 8)
        s[ty + i][tx] = W[(size_t)(k0 + ty + i) * FF + n0 + tx];
    __syncthreads();
#pragma unroll
    for (int i = 0; i < 32; i += 8)
        o[(size_t)(n0 + ty + i) * FF + k0 + tx] = f2bf(s[tx][ty + i]);
}

// Vt[z=(b,h)][d][m] = x1[b, m, h*128+d]
__global__ void conv_vt(const float* __restrict__ x1, unsigned short* oh) {
    __shared__ float s[32][33];
    int z = blockIdx.z, b = z >> 3, h = z & 7;
    int m0 = blockIdx.x * 32, d0 = blockIdx.y * 32;
    const float* src = x1 + (size_t)b * NN * FF + h * DD;
    int tx = threadIdx.x, ty = threadIdx.y;
#pragma unroll
    for (int i = 0; i < 32; i += 8)
        s[ty + i][tx] = src[(size_t)(m0 + ty + i) * FF + d0 + tx];
    __syncthreads();
    size_t zo = (size_t)z * DD * NN;
#pragma unroll
    for (int i = 0; i < 32; i += 8) {
        size_t o = zo + (size_t)(d0 + ty + i) * NN + m0 + tx;
        oh[o] = f2bf(s[tx][ty + i]);
    }
}

// ---------------------------------------------------------------------------
// Fused aff + mask + softmax. Per z=(b,h): CTA = 64 q-rows x 512 k-cols, K=128.
// 512 threads = 16 warps (4m x 4n), warp tile 16x128. Full operands in smem.
#define FA0 0
#define FA1 8192
#define FB0 16384
#define FB1 81920
#define FRED 147456
#define FRED2 148480
#define FS_BYTES 149504

__global__ void __launch_bounds__(512, 1)
aff_softmax(const unsigned short* __restrict__ qg, const unsigned short* __restrict__ kg,
            const unsigned int* __restrict__ maskb,
            float* __restrict__ att, unsigned short* __restrict__ attb) {
    extern __shared__ char smem[];
    uint32_t sbase = smem_u32(smem);
    int tid = threadIdx.x, lid = tid & 31, wid = tid >> 5;
    int wm = wid & 3, wn = wid >> 2;
    int z = blockIdx.z, b = z >> 3;
    const unsigned short* pA = qg + (size_t)b * NN * FF + (z & 7) * DD;
    const unsigned short* pB = kg + (size_t)b * NN * FF + (z & 7) * DD;
    const unsigned int* msk = maskb + (size_t)b * NN * NN;
    size_t attz = (size_t)z * NN * NN;
    int bm = blockIdx.y * 64;

    // async loads: chunk0 (k 0-63), commit; chunk1 (k 64-127), commit
    {
        int rowA = tid >> 3, chA = tid & 7;
        uint32_t dA = (uint32_t)rowA * 128 + ((uint32_t)(chA ^ (rowA & 7)) << 4);
        const unsigned short* sA = pA + (size_t)(bm + rowA) * FF + chA * 8;
        cpa16(sbase + FA0 + dA, sA);
#pragma unroll
        for (int t = 0; t < 8; t++) {
            int idx = tid + t * 512, row = idx >> 3, ch = idx & 7;
            cpa16(sbase + FB0 + (uint32_t)row * 128 + ((uint32_t)(ch ^ (row & 7)) << 4),
                  pB + (size_t)row * FF + ch * 8);
        }
        CP_COMMIT();
        cpa16(sbase + FA1 + dA, sA + 64);
#pragma unroll
        for (int t = 0; t < 8; t++) {
            int idx = tid + t * 512, row = idx >> 3, ch = idx & 7;
            cpa16(sbase + FB1 + (uint32_t)row * 128 + ((uint32_t)(ch ^ (row & 7)) << 4),
                  pB + (size_t)row * FF + 64 + ch * 8);
        }
        CP_COMMIT();
    }

    float acc[16][4];
#pragma unroll
    for (int i = 0; i < 16; i++)
#pragma unroll
        for (int j = 0; j < 4; j++) acc[i][j] = 0.f;

    int rowAl = ((lid >> 3) & 1) * 8 + (lid & 7);
    int aK = lid >> 4;
    int rowBl = ((lid >> 4) & 1) * 8 + (lid & 7);
    int bK = (lid >> 3) & 1;
    uint32_t swz = (uint32_t)(lid & 7);
    uint32_t offA = (uint32_t)(wm * 16 + rowAl) * 128;
    uint32_t offB = (uint32_t)(wn * 128 + rowBl) * 128;

    CP_WAIT(1);
    __syncthreads();
#pragma unroll
    for (int ck = 0; ck < 2; ck++) {
        uint32_t cA = sbase + (ck ? FA1 : FA0);
        uint32_t cB = sbase + (ck ? FB1 : FB0);
#pragma unroll
        for (int s = 0; s < 4; s++) {
            uint32_t a[4];
            ldsm4(a, cA + offA + (((uint32_t)(2 * s + aK) ^ swz) << 4));
            uint32_t kb = ((uint32_t)(2 * s + bK) ^ swz) << 4;
#pragma unroll
            for (int p = 0; p < 8; p++) {
                uint32_t bf[4];
                ldsm4(bf, cB + offB + (uint32_t)p * 2048 + kb);
                mma_bf16(acc[2 * p], a, bf);
                mma_bf16(acc[2 * p + 1], a, bf + 2);
            }
        }
        if (ck == 0) {
            CP_WAIT(0);
            __syncthreads();
        }
    }

    // ---- fused mask + softmax epilogue ----
    int g = lid >> 2, t = lid & 3;
    int lr = wm * 16 + g;          // local rows lr, lr+8
    int r0 = bm + lr, r1 = r0 + 8;
    float* rmax = reinterpret_cast<float*>(smem + FRED);
    float* rsum = reinterpret_cast<float*>(smem + FRED2);

    float mx0 = -INFINITY, mx1 = -INFINITY;
#pragma unroll
    for (int nf = 0; nf < 16; nf++) {
        int c = wn * 128 + nf * 8 + t * 2;
        uint2 m0 = *reinterpret_cast<const uint2*>(msk + (size_t)r0 * NN + c);
        uint2 m1 = *reinterpret_cast<const uint2*>(msk + (size_t)r1 * NN + c);
        if (m0.x) acc[nf][0] = -1e9f;
        if (m0.y) acc[nf][1] = -1e9f;
        if (m1.x) acc[nf][2] = -1e9f;
        if (m1.y) acc[nf][3] = -1e9f;
        mx0 = fmaxf(mx0, fmaxf(acc[nf][0], acc[nf][1]));
        mx1 = fmaxf(mx1, fmaxf(acc[nf][2], acc[nf][3]));
    }
    mx0 = fmaxf(mx0, __shfl_xor_sync(0xffffffffu, mx0, 1));
    mx0 = fmaxf(mx0, __shfl_xor_sync(0xffffffffu, mx0, 2));
    mx1 = fmaxf(mx1, __shfl_xor_sync(0xffffffffu, mx1, 1));
    mx1 = fmaxf(mx1, __shfl_xor_sync(0xffffffffu, mx1, 2));
    if (t == 0) {
        rmax[lr * 4 + wn] = mx0;
        rmax[(lr + 8) * 4 + wn] = mx1;
    }
    __syncthreads();
    {
        float4 q0 = *reinterpret_cast<float4*>(rmax + lr * 4);
        float4 q1 = *reinterpret_cast<float4*>(rmax + (lr + 8) * 4);
        mx0 = fmaxf(fmaxf(q0.x, q0.y), fmaxf(q0.z, q0.w));
        mx1 = fmaxf(fmaxf(q1.x, q1.y), fmaxf(q1.z, q1.w));
    }
    float s0 = 0.f, s1 = 0.f;
#pragma unroll
    for (int nf = 0; nf < 16; nf++) {
        acc[nf][0] = __expf(acc[nf][0] - mx0);
        acc[nf][1] = __expf(acc[nf][1] - mx0);
        acc[nf][2] = __expf(acc[nf][2] - mx1);
        acc[nf][3] = __expf(acc[nf][3] - mx1);
        s0 += acc[nf][0] + acc[nf][1];
        s1 += acc[nf][2] + acc[nf][3];
    }
    s0 += __shfl_xor_sync(0xffffffffu, s0, 1);
    s0 += __shfl_xor_sync(0xffffffffu, s0, 2);
    s1 += __shfl_xor_sync(0xffffffffu, s1, 1);
    s1 += __shfl_xor_sync(0xffffffffu, s1, 2);
    if (t == 0) {
        rsum[lr * 4 + wn] = s0;
        rsum[(lr + 8) * 4 + wn] = s1;
    }
    __syncthreads();
    float inv0, inv1;
    {
        float4 q0 = *reinterpret_cast<float4*>(rsum + lr * 4);
        float4 q1 = *reinterpret_cast<float4*>(rsum + (lr + 8) * 4);
        inv0 = 1.f / (q0.x + q0.y + q0.z + q0.w);
        inv1 = 1.f / (q1.x + q1.y + q1.z + q1.w);
    }
#pragma unroll
    for (int nf = 0; nf < 16; nf++) {
        int c = wn * 128 + nf * 8 + t * 2;
        float v0 = acc[nf][0] * inv0, v1 = acc[nf][1] * inv0;
        float v2 = acc[nf][2] * inv1, v3 = acc[nf][3] * inv1;
        *reinterpret_cast<float2*>(att + attz + (size_t)r0 * NN + c) = make_float2(v0, v1);
        *reinterpret_cast<float2*>(att + attz + (size_t)r1 * NN + c) = make_float2(v2, v3);
        *reinterpret_cast<uint32_t*>(attb + attz + (size_t)r0 * NN + c) = pack_bf2(v0, v1);
        *reinterpret_cast<uint32_t*>(attb + attz + (size_t)r1 * NN + c) = pack_bf2(v2, v3);
    }
}

// ---------------------------------------------------------------------------
// Warp-MMA bf16 GEMM. CTA tile 128x128, KC=64, 8 warps (4m x 2n, warp 32x64),
// double-buffered cp.async, XOR-swizzled smem (row pitch 128B, chunk^row&7).
// A[M,K], B[N,K] bf16. MODE: 0 Q-proj -> bf16; 2 att@V -> bf16;
// 3 relu(acc+bl)+x1 -> fp32.
#define KC 64
#define PLANE_B 16384   // 128 rows * 128 B
#define STAGE_B 32768   // A + B
#define SMEM_BYTES 65536

template <int MODE>
__global__ void __launch_bounds__(256, 2)
mma_gemm(const unsigned short* __restrict__ Ab, int lda, long sAz, long sAh2,
         const unsigned short* __restrict__ Bb, int ldb, long sBz, long sBh2,
         int K,
         float* __restrict__ Cf, unsigned short* __restrict__ Ch,
         int ldc, long sCz, long sCh2,
         const float* __restrict__ e0, const float* __restrict__ e1) {
    extern __shared__ char smem[];
    uint32_t sbase = smem_u32(smem);
    int tid = threadIdx.x;
    int lid = tid & 31, wid = tid >> 5;
    int wm = wid & 3, wn = wid >> 2;

    int z = blockIdx.z;
    const unsigned short* pA = Ab + (long)(z >> 3) * sAz + (long)(z & 7) * sAh2;
    const unsigned short* pB = Bb + (long)(z >> 3) * sBz + (long)(z & 7) * sBh2;
    long zC = (long)(z >> 3) * sCz + (long)(z & 7) * sCh2;

    int bm = blockIdx.y * 128;
    int bn = blockIdx.x * 128;

    float acc[2][8][4];
#pragma unroll
    for (int i = 0; i < 2; i++)
#pragma unroll
        for (int j = 0; j < 8; j++)
#pragma unroll
            for (int k = 0; k < 4; k++) acc[i][j][k] = 0.f;

    int rowAl = ((lid >> 3) & 1) * 8 + (lid & 7);
    int aK = lid >> 4;
    int rowBl = ((lid >> 4) & 1) * 8 + (lid & 7);
    int bK = (lid >> 3) & 1;
    uint32_t swz = (uint32_t)(lid & 7);
    uint32_t offA = (uint32_t)(wm * 32 + rowAl) * 128;
    uint32_t offBp[4];
#pragma unroll
    for (int p = 0; p < 4; p++)
        offBp[p] = PLANE_B + (uint32_t)(wn * 64 + p * 16 + rowBl) * 128;

#define LOAD_PLANE(dstoff, src, ld, row0, k0)                                   \
    {                                                                           \
        _Pragma("unroll") for (int t = 0; t < 4; t++) {                         \
            int idx = tid + t * 256;                                            \
            int row = idx >> 3, ch = idx & 7;                                   \
            uint32_t d = (dstoff) + (uint32_t)row * 128 +                       \
                         ((uint32_t)(ch ^ (row & 7)) << 4);                     \
            cpa16(d, (src) + (size_t)((row0) + row) * (ld) + (k0) + ch * 8);    \
        }                                                                       \
    }
#define LOAD_STAGE(st, k0)                                      \
    {                                                           \
        uint32_t sb_ = sbase + (uint32_t)(st) * STAGE_B;        \
        LOAD_PLANE(sb_, pA, lda, bm, k0);                       \
        LOAD_PLANE(sb_ + PLANE_B, pB, ldb, bn, k0);             \
    }

    int nch = K >> 6;
    LOAD_STAGE(0, 0);
    CP_COMMIT();

    for (int c = 0; c < nch; c++) {
        if (c + 1 < nch) {
            LOAD_STAGE((c + 1) & 1, (c + 1) * KC);
            CP_COMMIT();
            CP_WAIT(1);
        } else {
            CP_WAIT(0);
        }
        __syncthreads();

        uint32_t ss = sbase + (uint32_t)(c & 1) * STAGE_B;
#pragma unroll
        for (int s = 0; s < 4; s++) {
            uint32_t a0[4], a1[4], bF[16];
            uint32_t kchA = ((uint32_t)(2 * s + aK) ^ swz) << 4;
            uint32_t kchB = ((uint32_t)(2 * s + bK) ^ swz) << 4;
            ldsm4(a0, ss + offA + kchA);
            ldsm4(a1, ss + offA + 2048 + kchA);
#pragma unroll
            for (int p = 0; p < 4; p++) ldsm4(bF + p * 4, ss + offBp[p] + kchB);
#pragma unroll
            for (int nt = 0; nt < 8; nt++) {
                mma_bf16(acc[0][nt], a0, bF + nt * 2);
                mma_bf16(acc[1][nt], a1, bF + nt * 2);
            }
        }
        __syncthreads();
    }

    // epilogue
    int g = lid >> 2, t = lid & 3;
    const float SCALE = 0.08838834764831845f;  // 1/sqrt(128)
#pragma unroll
    for (int mt = 0; mt < 2; mt++) {
#pragma unroll
        for (int h2 = 0; h2 < 2; h2++) {
            int r = bm + wm * 32 + mt * 16 + g + h2 * 8;
#pragma unroll
            for (int nt = 0; nt < 8; nt++) {
                int c = bn + wn * 64 + nt * 8 + t * 2;
                float v0 = acc[mt][nt][h2 * 2 + 0];
                float v1 = acc[mt][nt][h2 * 2 + 1];
                size_t co = (size_t)zC + (size_t)r * ldc + c;
                if (MODE == 0) {
                    int gb = (r >> 9) << 10;
                    v0 = (v0 + e0[c]) * e1[gb + c] * SCALE;
                    v1 = (v1 + e0[c + 1]) * e1[gb + c + 1] * SCALE;
                    *reinterpret_cast<uint32_t*>(Ch + co) = pack_bf2(v0, v1);
                } else if (MODE == 2) {
                    *reinterpret_cast<uint32_t*>(Ch + co) = pack_bf2(v0, v1);
                } else {
                    size_t ro = (size_t)r * FF + c;
                    v0 = fmaxf(v0 + e0[c], 0.f) + e1[ro];
                    v1 = fmaxf(v1 + e0[c + 1], 0.f) + e1[ro + 1];
                    *reinterpret_cast<float2*>(Cf + co) = make_float2(v0, v1);
                }
            }
        }
    }
}

// ---------------------------------------------------------------------------
extern "C" void kernel_launch(void* const* d_in, const int* in_sizes, int n_in,
                              void* d_out, int out_size) {
    const float* x1 = (const float*)d_in[0];
    const float* x2 = (const float*)d_in[1];
    const unsigned int* mask = (const unsigned int*)d_in[4];
    const float* Wq = (const float*)d_in[5];
    const float* bq = (const float*)d_in[6];
    const float* Wl = (const float*)d_in[7];
    const float* bl = (const float*)d_in[8];

    float* out_x = (float*)d_out;
    float* out_att = (float*)d_out + ((size_t)out_size - (size_t)BB * HH * NN * NN);

    float* p_gate;
    unsigned short *x1h, *kgh, *qgh, *vth, *vbh, *wqth, *wlth, *atth;
    cudaGetSymbolAddress((void**)&p_gate, g_gate);
    cudaGetSymbolAddress((void**)&x1h, g_x1h);
    cudaGetSymbolAddress((void**)&kgh, g_kgh);
    cudaGetSymbolAddress((void**)&qgh, g_qgh);
    cudaGetSymbolAddress((void**)&vth, g_vth);
    cudaGetSymbolAddress((void**)&vbh, g_vbh);
    cudaGetSymbolAddress((void**)&wqth, g_wqth);
    cudaGetSymbolAddress((void**)&wlth, g_wlth);
    cudaGetSymbolAddress((void**)&atth, g_atth);

    cudaFuncSetAttribute(mma_gemm<0>, cudaFuncAttributeMaxDynamicSharedMemorySize, SMEM_BYTES);
    cudaFuncSetAttribute(mma_gemm<2>, cudaFuncAttributeMaxDynamicSharedMemorySize, SMEM_BYTES);
    cudaFuncSetAttribute(mma_gemm<3>, cudaFuncAttributeMaxDynamicSharedMemorySize, SMEM_BYTES);
    cudaFuncSetAttribute(aff_softmax, cudaFuncAttributeMaxDynamicSharedMemorySize, FS_BYTES);

    // 1) gate
    gate_kernel<<<BB, 1024>>>(x2, p_gate);
    // 2) conversions to bf16
    conv_x1<<<(BB * NN * FF) / 256, 256>>>(x1, p_gate, x1h, kgh);
    conv_wq<<<dim3(FF / 32, DD / 32, HH), dim3(32, 8)>>>(Wq, wqth);
    conv_wl<<<dim3(FF / 32, FF / 32), dim3(32, 8)>>>(Wl, wlth);
    conv_vt<<<dim3(NN / 32, DD / 32, BB * HH), dim3(32, 8)>>>(x1, vth);
    // 3) Qg = (x1 @ Wqt + bq) * gate * scale -> bf16   [16384x1024x1024]
    mma_gemm<0><<<dim3(8, 128, 1), 256, SMEM_BYTES>>>(
        x1h, 1024, 0, 0, wqth, 1024, 0, 0, 1024,
        nullptr, qgh, 1024, 0, 0, bq, p_gate);
    // 4) fused aff + mask + softmax -> att fp32 (output) + att bf16
    aff_softmax<<<dim3(1, NN / 64, BB * HH), 512, FS_BYTES>>>(
        qgh, kgh, mask, out_att, atth);
    // 5) vb = att @ V -> bf16   [512x128x512] x 256
    mma_gemm<2><<<dim3(1, 4, 256), 256, SMEM_BYTES>>>(
        atth, 512, 8L * NN * NN, (long)NN * NN, vth, 512, 8L * DD * NN, (long)DD * NN, 512,
        nullptr, vbh, 1024, (long)NN * FF, DD,
        nullptr, nullptr);
    // 6) xout = relu(vb @ Wlt + bl) + x1   [16384x1024x1024]
    mma_gemm<3><<<dim3(8, 128, 1), 256, SMEM_BYTES>>>(
        vbh, 1024, 0, 0, wlth, 1024, 0, 0, 1024,
        out_x, nullptr, 1024, 0, 0, bl, x1);
}

// round 11
// speedup vs baseline: 1.5067x; 1.5067x over previous
#include <cuda_runtime.h>
#include <cuda_bf16.h>
#include <math.h>
#include <cstdint>

#define BB 32
#define NN 512
#define FF 1024
#define HH 8
#define DD 128

// ---------------------------------------------------------------------------
// Device scratch (allocation-free), single bf16 plane each
__device__ unsigned short g_x1h[BB * NN * FF];
__device__ unsigned short g_kgh[BB * NN * FF];
__device__ unsigned short g_qgh[BB * NN * FF];
__device__ unsigned short g_vth[BB * NN * FF];
__device__ unsigned short g_vbh[BB * NN * FF];
__device__ unsigned short g_wqth[FF * FF];
__device__ unsigned short g_wlth[FF * FF];
__device__ unsigned short g_atth[(size_t)BB * HH * NN * NN];  // logits, then att (bf16)
__device__ float g_gate[BB * FF];
__device__ float g_gpart[BB * 8 * FF];

__device__ __forceinline__ unsigned short f2bf(float v) {
    __nv_bfloat16 h = __float2bfloat16(v);
    return *reinterpret_cast<unsigned short*>(&h);
}
// packed: lo 16 bits = bf16(v0), hi = bf16(v1)
__device__ __forceinline__ uint32_t pack_bf2(float v0, float v1) {
    uint32_t r;
    asm("cvt.rn.bf16x2.f32 %0, %1, %2;" : "=r"(r) : "f"(v1), "f"(v0));
    return r;
}
__device__ __forceinline__ float bf_lo(uint32_t w) { return __uint_as_float(w << 16); }
__device__ __forceinline__ float bf_hi(uint32_t w) { return __uint_as_float(w & 0xFFFF0000u); }

__device__ __forceinline__ uint32_t smem_u32(const void* p) {
    uint32_t a;
    asm("{ .reg .u64 t; cvta.to.shared.u64 t, %1; cvt.u32.u64 %0, t; }" : "=r"(a) : "l"(p));
    return a;
}
__device__ __forceinline__ void cpa16(uint32_t dst, const void* src) {
    asm volatile("cp.async.cg.shared.global [%0], [%1], 16;" :: "r"(dst), "l"(src));
}
#define CP_COMMIT() asm volatile("cp.async.commit_group;" ::: "memory")
#define CP_WAIT(n) asm volatile("cp.async.wait_group %0;" :: "n"(n) : "memory")

__device__ __forceinline__ void ldsm4(uint32_t* r, uint32_t addr) {
    asm volatile("ldmatrix.sync.aligned.m8n8.x4.shared.b16 {%0,%1,%2,%3}, [%4];"
                 : "=r"(r[0]), "=r"(r[1]), "=r"(r[2]), "=r"(r[3]) : "r"(addr));
}
__device__ __forceinline__ void mma_bf16(float* d, const uint32_t* a, const uint32_t* b) {
    asm volatile(
        "mma.sync.aligned.m16n8k16.row.col.f32.bf16.bf16.f32 "
        "{%0,%1,%2,%3}, {%4,%5,%6,%7}, {%8,%9}, {%0,%1,%2,%3};"
        : "+f"(d[0]), "+f"(d[1]), "+f"(d[2]), "+f"(d[3])
        : "r"(a[0]), "r"(a[1]), "r"(a[2]), "r"(a[3]), "r"(b[0]), "r"(b[1]));
}

// ---------------------------------------------------------------------------
// gate = mean(x2, axis=1), two-pass (deterministic, concurrency-friendly)
__global__ void gate_part(const float* __restrict__ x2, float* __restrict__ part) {
    int s = blockIdx.x, b = blockIdx.y, f = threadIdx.x;
    const float* p = x2 + ((size_t)b * NN + s * 64) * FF + f;
    float sum = 0.f;
#pragma unroll 8
    for (int n = 0; n < 64; n++) sum += p[(size_t)n * FF];
    part[((size_t)b * 8 + s) * FF + f] = sum;
}
__global__ void gate_reduce(const float* __restrict__ part, float* __restrict__ gate) {
    int b = blockIdx.x, f = threadIdx.x;
    float s = 0.f;
#pragma unroll
    for (int i = 0; i < 8; i++) s += part[((size_t)b * 8 + i) * FF + f];
    gate[b * FF + f] = s * (1.0f / NN);
}

__global__ void conv_x1(const float* __restrict__ x1, const float* __restrict__ gate,
                        unsigned short* xh, unsigned short* kh) {
    size_t i = (size_t)blockIdx.x * 256 + threadIdx.x;
    int c = (int)(i & (FF - 1));
    int b = (int)(i >> 19);
    float v = x1[i];
    xh[i] = f2bf(v);
    kh[i] = f2bf(v * gate[b * FF + c]);
}

// Wqt[h*128+d][f] = Wq[h][f][d]  (tiled transpose)
__global__ void conv_wq(const float* __restrict__ W, unsigned short* __restrict__ o) {
    __shared__ float s[32][33];
    int h = blockIdx.z;
    int f0 = blockIdx.x * 32, d0 = blockIdx.y * 32;
    int tx = threadIdx.x, ty = threadIdx.y;
#pragma unroll
    for (int i = 0; i < 32; i += 8)
        s[ty + i][tx] = W[((size_t)h * FF + f0 + ty + i) * DD + d0 + tx];
    __syncthreads();
#pragma unroll
    for (int i = 0; i < 32; i += 8)
        o[(size_t)(h * DD + d0 + ty + i) * FF + f0 + tx] = f2bf(s[tx][ty + i]);
}

// Wlt[n][k] = Wl[k][n]  (tiled transpose)
__global__ void conv_wl(const float* __restrict__ W, unsigned short* __restrict__ o) {
    __shared__ float s[32][33];
    int k0 = blockIdx.x * 32, n0 = blockIdx.y * 32;
    int tx = threadIdx.x, ty = threadIdx.y;
#pragma unroll
    for (int i = 0; i < 32; i += 8)
        s[ty + i][tx] = W[(size_t)(k0 + ty + i) * FF + n0 + tx];
    __syncthreads();
#pragma unroll
    for (int i = 0; i < 32; i += 8)
        o[(size_t)(n0 + ty + i) * FF + k0 + tx] = f2bf(s[tx][ty + i]);
}

// Vt[z=(b,h)][d][m] = x1[b, m, h*128+d]
__global__ void conv_vt(const float* __restrict__ x1, unsigned short* oh) {
    __shared__ float s[32][33];
    int z = blockIdx.z, b = z >> 3, h = z & 7;
    int m0 = blockIdx.x * 32, d0 = blockIdx.y * 32;
    const float* src = x1 + (size_t)b * NN * FF + h * DD;
    int tx = threadIdx.x, ty = threadIdx.y;
#pragma unroll
    for (int i = 0; i < 32; i += 8)
        s[ty + i][tx] = src[(size_t)(m0 + ty + i) * FF + d0 + tx];
    __syncthreads();
    size_t zo = (size_t)z * DD * NN;
#pragma unroll
    for (int i = 0; i < 32; i += 8) {
        size_t o = zo + (size_t)(d0 + ty + i) * NN + m0 + tx;
        oh[o] = f2bf(s[tx][ty + i]);
    }
}

// ---------------------------------------------------------------------------
// softmax: read bf16 masked logits, write fp32 att + bf16 att (in place on lg).
// One warp per row of 512.
__global__ void softmax_kernel(const unsigned short* __restrict__ lg,
                               float* __restrict__ att,
                               unsigned short* __restrict__ ab) {
    int row = blockIdx.x * 8 + (threadIdx.x >> 5);
    int lane = threadIdx.x & 31;
    size_t base = (size_t)row * NN;
    const uint32_t* pl = reinterpret_cast<const uint32_t*>(lg + base);
    uint32_t* pb = reinterpret_cast<uint32_t*>(ab + base);
    float v[16];
    float mx = -INFINITY;
#pragma unroll
    for (int k = 0; k < 8; k++) {
        uint32_t w = pl[lane + k * 32];
        v[2 * k] = bf_lo(w);
        v[2 * k + 1] = bf_hi(w);
        mx = fmaxf(mx, fmaxf(v[2 * k], v[2 * k + 1]));
    }
#pragma unroll
    for (int o = 16; o; o >>= 1) mx = fmaxf(mx, __shfl_xor_sync(0xffffffffu, mx, o));
    float s = 0.f;
#pragma unroll
    for (int i = 0; i < 16; i++) {
        v[i] = __expf(v[i] - mx);
        s += v[i];
    }
#pragma unroll
    for (int o = 16; o; o >>= 1) s += __shfl_xor_sync(0xffffffffu, s, o);
    float inv = 1.f / s;
#pragma unroll
    for (int k = 0; k < 8; k++) {
        float a = v[2 * k] * inv, b = v[2 * k + 1] * inv;
        int c0 = 2 * (lane + k * 32);
        *reinterpret_cast<float2*>(att + base + c0) = make_float2(a, b);
        pb[lane + k * 32] = pack_bf2(a, b);
    }
}

// ---------------------------------------------------------------------------
// Warp-MMA bf16 GEMM. CTA tile 128x128, KC=64, 8 warps (4m x 2n, warp 32x64),
// double-buffered cp.async, XOR-swizzled smem (row pitch 128B, chunk^row&7).
// A[M,K], B[N,K] bf16. MODE: 0 Q-proj -> bf16; 1 aff+mask -> bf16 logits;
// 2 att@V -> bf16; 3 relu(acc+bl)+x1 -> fp32.
#define KC 64
#define PLANE_B 16384   // 128 rows * 128 B
#define STAGE_B 32768   // A + B
#define SMEM_BYTES 65536

template <int MODE>
__global__ void __launch_bounds__(256, 2)
mma_gemm(const unsigned short* __restrict__ Ab, int lda, long sAz, long sAh2,
         const unsigned short* __restrict__ Bb, int ldb, long sBz, long sBh2,
         int K,
         float* __restrict__ Cf, unsigned short* __restrict__ Ch,
         int ldc, long sCz, long sCh2,
         const float* __restrict__ e0, const float* __restrict__ e1,
         const unsigned int* __restrict__ maskb) {
    extern __shared__ char smem[];
    uint32_t sbase = smem_u32(smem);
    int tid = threadIdx.x;
    int lid = tid & 31, wid = tid >> 5;
    int wm = wid & 3, wn = wid >> 2;

    int z = blockIdx.z;
    const unsigned short* pA = Ab + (long)(z >> 3) * sAz + (long)(z & 7) * sAh2;
    const unsigned short* pB = Bb + (long)(z >> 3) * sBz + (long)(z & 7) * sBh2;
    long zC = (long)(z >> 3) * sCz + (long)(z & 7) * sCh2;
    const unsigned int* msk = (MODE == 1) ? (maskb + (size_t)(z >> 3) * NN * NN) : nullptr;

    int bm = blockIdx.y * 128;
    int bn = blockIdx.x * 128;

    float acc[2][8][4];
#pragma unroll
    for (int i = 0; i < 2; i++)
#pragma unroll
        for (int j = 0; j < 8; j++)
#pragma unroll
            for (int k = 0; k < 4; k++) acc[i][j][k] = 0.f;

    int rowAl = ((lid >> 3) & 1) * 8 + (lid & 7);
    int aK = lid >> 4;
    int rowBl = ((lid >> 4) & 1) * 8 + (lid & 7);
    int bK = (lid >> 3) & 1;
    uint32_t swz = (uint32_t)(lid & 7);
    uint32_t offA = (uint32_t)(wm * 32 + rowAl) * 128;
    uint32_t offBp[4];
#pragma unroll
    for (int p = 0; p < 4; p++)
        offBp[p] = PLANE_B + (uint32_t)(wn * 64 + p * 16 + rowBl) * 128;

#define LOAD_PLANE(dstoff, src, ld, row0, k0)                                   \
    {                                                                           \
        _Pragma("unroll") for (int t = 0; t < 4; t++) {                         \
            int idx = tid + t * 256;                                            \
            int row = idx >> 3, ch = idx & 7;                                   \
            uint32_t d = (dstoff) + (uint32_t)row * 128 +                       \
                         ((uint32_t)(ch ^ (row & 7)) << 4);                     \
            cpa16(d, (src) + (size_t)((row0) + row) * (ld) + (k0) + ch * 8);    \
        }                                                                       \
    }
#define LOAD_STAGE(st, k0)                                      \
    {                                                           \
        uint32_t sb_ = sbase + (uint32_t)(st) * STAGE_B;        \
        LOAD_PLANE(sb_, pA, lda, bm, k0);                       \
        LOAD_PLANE(sb_ + PLANE_B, pB, ldb, bn, k0);             \
    }

    int nch = K >> 6;
    LOAD_STAGE(0, 0);
    CP_COMMIT();

    for (int c = 0; c < nch; c++) {
        if (c + 1 < nch) {
            LOAD_STAGE((c + 1) & 1, (c + 1) * KC);
            CP_COMMIT();
            CP_WAIT(1);
        } else {
            CP_WAIT(0);
        }
        __syncthreads();

        uint32_t ss = sbase + (uint32_t)(c & 1) * STAGE_B;
#pragma unroll
        for (int s = 0; s < 4; s++) {
            uint32_t a0[4], a1[4], bF[16];
            uint32_t kchA = ((uint32_t)(2 * s + aK) ^ swz) << 4;
            uint32_t kchB = ((uint32_t)(2 * s + bK) ^ swz) << 4;
            ldsm4(a0, ss + offA + kchA);
            ldsm4(a1, ss + offA + 2048 + kchA);
#pragma unroll
            for (int p = 0; p < 4; p++) ldsm4(bF + p * 4, ss + offBp[p] + kchB);
#pragma unroll
            for (int nt = 0; nt < 8; nt++) {
                mma_bf16(acc[0][nt], a0, bF + nt * 2);
                mma_bf16(acc[1][nt], a1, bF + nt * 2);
            }
        }
        __syncthreads();
    }

    // epilogue
    int g = lid >> 2, t = lid & 3;
    const float SCALE = 0.08838834764831845f;  // 1/sqrt(128)
#pragma unroll
    for (int mt = 0; mt < 2; mt++) {
#pragma unroll
        for (int h2 = 0; h2 < 2; h2++) {
            int r = bm + wm * 32 + mt * 16 + g + h2 * 8;
#pragma unroll
            for (int nt = 0; nt < 8; nt++) {
                int c = bn + wn * 64 + nt * 8 + t * 2;
                float v0 = acc[mt][nt][h2 * 2 + 0];
                float v1 = acc[mt][nt][h2 * 2 + 1];
                size_t co = (size_t)zC + (size_t)r * ldc + c;
                if (MODE == 0) {
                    int gb = (r >> 9) << 10;
                    v0 = (v0 + e0[c]) * e1[gb + c] * SCALE;
                    v1 = (v1 + e0[c + 1]) * e1[gb + c + 1] * SCALE;
                    *reinterpret_cast<uint32_t*>(Ch + co) = pack_bf2(v0, v1);
                } else if (MODE == 1) {
                    uint2 mm = *reinterpret_cast<const uint2*>(msk + (size_t)r * NN + c);
                    v0 = mm.x ? -1e9f : v0;
                    v1 = mm.y ? -1e9f : v1;
                    *reinterpret_cast<uint32_t*>(Ch + co) = pack_bf2(v0, v1);
                } else if (MODE == 2) {
                    *reinterpret_cast<uint32_t*>(Ch + co) = pack_bf2(v0, v1);
                } else {
                    size_t ro = (size_t)r * FF + c;
                    v0 = fmaxf(v0 + e0[c], 0.f) + e1[ro];
                    v1 = fmaxf(v1 + e0[c + 1], 0.f) + e1[ro + 1];
                    *reinterpret_cast<float2*>(Cf + co) = make_float2(v0, v1);
                }
            }
        }
    }
}

// ---------------------------------------------------------------------------
extern "C" void kernel_launch(void* const* d_in, const int* in_sizes, int n_in,
                              void* d_out, int out_size) {
    const float* x1 = (const float*)d_in[0];
    const float* x2 = (const float*)d_in[1];
    const unsigned int* mask = (const unsigned int*)d_in[4];
    const float* Wq = (const float*)d_in[5];
    const float* bq = (const float*)d_in[6];
    const float* Wl = (const float*)d_in[7];
    const float* bl = (const float*)d_in[8];

    float* out_x = (float*)d_out;
    float* out_att = (float*)d_out + ((size_t)out_size - (size_t)BB * HH * NN * NN);

    float *p_gate, *p_gpart;
    unsigned short *x1h, *kgh, *qgh, *vth, *vbh, *wqth, *wlth, *atth;
    cudaGetSymbolAddress((void**)&p_gate, g_gate);
    cudaGetSymbolAddress((void**)&p_gpart, g_gpart);
    cudaGetSymbolAddress((void**)&x1h, g_x1h);
    cudaGetSymbolAddress((void**)&kgh, g_kgh);
    cudaGetSymbolAddress((void**)&qgh, g_qgh);
    cudaGetSymbolAddress((void**)&vth, g_vth);
    cudaGetSymbolAddress((void**)&vbh, g_vbh);
    cudaGetSymbolAddress((void**)&wqth, g_wqth);
    cudaGetSymbolAddress((void**)&wlth, g_wlth);
    cudaGetSymbolAddress((void**)&atth, g_atth);

    cudaFuncSetAttribute(mma_gemm<0>, cudaFuncAttributeMaxDynamicSharedMemorySize, SMEM_BYTES);
    cudaFuncSetAttribute(mma_gemm<1>, cudaFuncAttributeMaxDynamicSharedMemorySize, SMEM_BYTES);
    cudaFuncSetAttribute(mma_gemm<2>, cudaFuncAttributeMaxDynamicSharedMemorySize, SMEM_BYTES);
    cudaFuncSetAttribute(mma_gemm<3>, cudaFuncAttributeMaxDynamicSharedMemorySize, SMEM_BYTES);

    // 1) gate = mean(x2, axis=1), two-pass
    gate_part<<<dim3(8, BB), 1024>>>(x2, p_gpart);
    gate_reduce<<<BB, 1024>>>(p_gpart, p_gate);
    // 2) conversions to bf16
    conv_x1<<<(BB * NN * FF) / 256, 256>>>(x1, p_gate, x1h, kgh);
    conv_wq<<<dim3(FF / 32, DD / 32, HH), dim3(32, 8)>>>(Wq, wqth);
    conv_wl<<<dim3(FF / 32, FF / 32), dim3(32, 8)>>>(Wl, wlth);
    conv_vt<<<dim3(NN / 32, DD / 32, BB * HH), dim3(32, 8)>>>(x1, vth);
    // 3) Qg = (x1 @ Wqt + bq) * gate * scale -> bf16   [16384x1024x1024]
    mma_gemm<0><<<dim3(8, 128, 1), 256, SMEM_BYTES>>>(
        x1h, 1024, 0, 0, wqth, 1024, 0, 0, 1024,
        nullptr, qgh, 1024, 0, 0, bq, p_gate, nullptr);
    // 4) aff = Qg @ Kg^T, mask fused -> bf16 logits   [512x512x128] x 256
    mma_gemm<1><<<dim3(4, 4, 256), 256, SMEM_BYTES>>>(
        qgh, 1024, (long)NN * FF, DD, kgh, 1024, (long)NN * FF, DD, 128,
        nullptr, atth, 512, 8L * NN * NN, (long)NN * NN,
        nullptr, nullptr, mask);
    // 5) softmax: bf16 logits -> fp32 att (output) + bf16 att (in place)
    softmax_kernel<<<(BB * HH * NN) / 8, 256>>>(atth, out_att, atth);
    // 6) vb = att @ V -> bf16   [512x128x512] x 256
    mma_gemm<2><<<dim3(1, 4, 256), 256, SMEM_BYTES>>>(
        atth, 512, 8L * NN * NN, (long)NN * NN, vth, 512, 8L * DD * NN, (long)DD * NN, 512,
        nullptr, vbh, 1024, (long)NN * FF, DD,
        nullptr, nullptr, nullptr);
    // 7) xout = relu(vb @ Wlt + bl) + x1   [16384x1024x1024]
    mma_gemm<3><<<dim3(8, 128, 1), 256, SMEM_BYTES>>>(
        vbh, 1024, 0, 0, wlth, 1024, 0, 0, 1024,
        out_x, nullptr, 1024, 0, 0, bl, x1, nullptr);
}

// round 12
// speedup vs baseline: 1.5721x; 1.0434x over previous
#include <cuda_runtime.h>
#include <cuda_bf16.h>
#include <math.h>
#include <cstdint>

#define BB 32
#define NN 512
#define FF 1024
#define HH 8
#define DD 128

// ---------------------------------------------------------------------------
// Device scratch (allocation-free), single bf16 plane each
__device__ unsigned short g_x1h[BB * NN * FF];
__device__ unsigned short g_qgh[BB * NN * FF];
__device__ unsigned short g_vth[BB * NN * FF];
__device__ unsigned short g_vbh[BB * NN * FF];
__device__ unsigned short g_wqth[FF * FF];
__device__ unsigned short g_wlth[FF * FF];
__device__ unsigned short g_lgt[(size_t)BB * HH * NN * NN];   // masked logits (bf16)
__device__ unsigned short g_atth[(size_t)BB * HH * NN * NN];  // att (bf16)
__device__ float g_gate[BB * FF];
__device__ float g_gpart[BB * 8 * FF];

__device__ __forceinline__ unsigned short f2bf(float v) {
    __nv_bfloat16 h = __float2bfloat16(v);
    return *reinterpret_cast<unsigned short*>(&h);
}
// packed: lo 16 bits = bf16(v0), hi = bf16(v1)
__device__ __forceinline__ uint32_t pack_bf2(float v0, float v1) {
    uint32_t r;
    asm("cvt.rn.bf16x2.f32 %0, %1, %2;" : "=r"(r) : "f"(v1), "f"(v0));
    return r;
}
__device__ __forceinline__ float bf_lo(uint32_t w) { return __uint_as_float(w << 16); }
__device__ __forceinline__ float bf_hi(uint32_t w) { return __uint_as_float(w & 0xFFFF0000u); }

__device__ __forceinline__ uint32_t smem_u32(const void* p) {
    uint32_t a;
    asm("{ .reg .u64 t; cvta.to.shared.u64 t, %1; cvt.u32.u64 %0, t; }" : "=r"(a) : "l"(p));
    return a;
}
__device__ __forceinline__ void cpa16(uint32_t dst, const void* src) {
    asm volatile("cp.async.cg.shared.global [%0], [%1], 16;" :: "r"(dst), "l"(src));
}
#define CP_COMMIT() asm volatile("cp.async.commit_group;" ::: "memory")
#define CP_WAIT(n) asm volatile("cp.async.wait_group %0;" :: "n"(n) : "memory")

__device__ __forceinline__ void ldsm4(uint32_t* r, uint32_t addr) {
    asm volatile("ldmatrix.sync.aligned.m8n8.x4.shared.b16 {%0,%1,%2,%3}, [%4];"
                 : "=r"(r[0]), "=r"(r[1]), "=r"(r[2]), "=r"(r[3]) : "r"(addr));
}
__device__ __forceinline__ void mma_bf16(float* d, const uint32_t* a, const uint32_t* b) {
    asm volatile(
        "mma.sync.aligned.m16n8k16.row.col.f32.bf16.bf16.f32 "
        "{%0,%1,%2,%3}, {%4,%5,%6,%7}, {%8,%9}, {%0,%1,%2,%3};"
        : "+f"(d[0]), "+f"(d[1]), "+f"(d[2]), "+f"(d[3])
        : "r"(a[0]), "r"(a[1]), "r"(a[2]), "r"(a[3]), "r"(b[0]), "r"(b[1]));
}

// ---------------------------------------------------------------------------
// gate = mean(x2, axis=1), two-pass (deterministic)
__global__ void gate_part(const float* __restrict__ x2, float* __restrict__ part) {
    int s = blockIdx.x, b = blockIdx.y, f = threadIdx.x;
    const float* p = x2 + ((size_t)b * NN + s * 64) * FF + f;
    float sum = 0.f;
#pragma unroll 8
    for (int n = 0; n < 64; n++) sum += p[(size_t)n * FF];
    part[((size_t)b * 8 + s) * FF + f] = sum;
}
__global__ void gate_reduce(const float* __restrict__ part, float* __restrict__ gate) {
    int b = blockIdx.x, f = threadIdx.x;
    float s = 0.f;
#pragma unroll
    for (int i = 0; i < 8; i++) s += part[((size_t)b * 8 + i) * FF + f];
    gate[b * FF + f] = s * (1.0f / NN);
}

// x1 -> bf16, vectorized (no gate dependency)
__global__ void conv_x1(const float4* __restrict__ x1, uint2* __restrict__ xh) {
    size_t i = (size_t)blockIdx.x * 256 + threadIdx.x;
    float4 v = x1[i];
    xh[i] = make_uint2(pack_bf2(v.x, v.y), pack_bf2(v.z, v.w));
}

// Wqt[h*128+d][f] = Wq[h][f][d]  (tiled transpose)
__global__ void conv_wq(const float* __restrict__ W, unsigned short* __restrict__ o) {
    __shared__ float s[32][33];
    int h = blockIdx.z;
    int f0 = blockIdx.x * 32, d0 = blockIdx.y * 32;
    int tx = threadIdx.x, ty = threadIdx.y;
#pragma unroll
    for (int i = 0; i < 32; i += 8)
        s[ty + i][tx] = W[((size_t)h * FF + f0 + ty + i) * DD + d0 + tx];
    __syncthreads();
#pragma unroll
    for (int i = 0; i < 32; i += 8)
        o[(size_t)(h * DD + d0 + ty + i) * FF + f0 + tx] = f2bf(s[tx][ty + i]);
}

// Wlt[n][k] = Wl[k][n]  (tiled transpose)
__global__ void conv_wl(const float* __restrict__ W, unsigned short* __restrict__ o) {
    __shared__ float s[32][33];
    int k0 = blockIdx.x * 32, n0 = blockIdx.y * 32;
    int tx = threadIdx.x, ty = threadIdx.y;
#pragma unroll
    for (int i = 0; i < 32; i += 8)
        s[ty + i][tx] = W[(size_t)(k0 + ty + i) * FF + n0 + tx];
    __syncthreads();
#pragma unroll
    for (int i = 0; i < 32; i += 8)
        o[(size_t)(n0 + ty + i) * FF + k0 + tx] = f2bf(s[tx][ty + i]);
}

// Vt[z=(b,h)][d][m] = x1[b, m, h*128+d]
__global__ void conv_vt(const float* __restrict__ x1, unsigned short* oh) {
    __shared__ float s[32][33];
    int z = blockIdx.z, b = z >> 3, h = z & 7;
    int m0 = blockIdx.x * 32, d0 = blockIdx.y * 32;
    const float* src = x1 + (size_t)b * NN * FF + h * DD;
    int tx = threadIdx.x, ty = threadIdx.y;
#pragma unroll
    for (int i = 0; i < 32; i += 8)
        s[ty + i][tx] = src[(size_t)(m0 + ty + i) * FF + d0 + tx];
    __syncthreads();
    size_t zo = (size_t)z * DD * NN;
#pragma unroll
    for (int i = 0; i < 32; i += 8) {
        size_t o = zo + (size_t)(d0 + ty + i) * NN + m0 + tx;
        oh[o] = f2bf(s[tx][ty + i]);
    }
}

// ---------------------------------------------------------------------------
// softmax (bf16 out): read bf16 logits, write bf16 att (separate buffer).
__global__ void softmax_bf16(const unsigned short* __restrict__ lg,
                             unsigned short* __restrict__ ab) {
    int row = blockIdx.x * 8 + (threadIdx.x >> 5);
    int lane = threadIdx.x & 31;
    size_t base = (size_t)row * NN;
    const uint32_t* pl = reinterpret_cast<const uint32_t*>(lg + base);
    uint32_t* pb = reinterpret_cast<uint32_t*>(ab + base);
    float v[16];
    float mx = -INFINITY;
#pragma unroll
    for (int k = 0; k < 8; k++) {
        uint32_t w = pl[lane + k * 32];
        v[2 * k] = bf_lo(w);
        v[2 * k + 1] = bf_hi(w);
        mx = fmaxf(mx, fmaxf(v[2 * k], v[2 * k + 1]));
    }
#pragma unroll
    for (int o = 16; o; o >>= 1) mx = fmaxf(mx, __shfl_xor_sync(0xffffffffu, mx, o));
    float s = 0.f;
#pragma unroll
    for (int i = 0; i < 16; i++) {
        v[i] = __expf(v[i] - mx);
        s += v[i];
    }
#pragma unroll
    for (int o = 16; o; o >>= 1) s += __shfl_xor_sync(0xffffffffu, s, o);
    float inv = 1.f / s;
#pragma unroll
    for (int k = 0; k < 8; k++)
        pb[lane + k * 32] = pack_bf2(v[2 * k] * inv, v[2 * k + 1] * inv);
}

// softmax (fp32 out): read bf16 logits, write fp32 att (mandatory output).
__global__ void softmax_f32(const unsigned short* __restrict__ lg,
                            float* __restrict__ att) {
    int row = blockIdx.x * 8 + (threadIdx.x >> 5);
    int lane = threadIdx.x & 31;
    size_t base = (size_t)row * NN;
    const uint32_t* pl = reinterpret_cast<const uint32_t*>(lg + base);
    float v[16];
    float mx = -INFINITY;
#pragma unroll
    for (int k = 0; k < 8; k++) {
        uint32_t w = pl[lane + k * 32];
        v[2 * k] = bf_lo(w);
        v[2 * k + 1] = bf_hi(w);
        mx = fmaxf(mx, fmaxf(v[2 * k], v[2 * k + 1]));
    }
#pragma unroll
    for (int o = 16; o; o >>= 1) mx = fmaxf(mx, __shfl_xor_sync(0xffffffffu, mx, o));
    float s = 0.f;
#pragma unroll
    for (int i = 0; i < 16; i++) {
        v[i] = __expf(v[i] - mx);
        s += v[i];
    }
#pragma unroll
    for (int o = 16; o; o >>= 1) s += __shfl_xor_sync(0xffffffffu, s, o);
    float inv = 1.f / s;
#pragma unroll
    for (int k = 0; k < 8; k++) {
        int c0 = 2 * (lane + k * 32);
        *reinterpret_cast<float2*>(att + base + c0) =
            make_float2(v[2 * k] * inv, v[2 * k + 1] * inv);
    }
}

// ---------------------------------------------------------------------------
// Warp-MMA bf16 GEMM. CTA tile 128x128, KC=64, 8 warps (4m x 2n, warp 32x64),
// double-buffered cp.async, XOR-swizzled smem (row pitch 128B, chunk^row&7).
// A[M,K], B[N,K] bf16. MODE: 0 Q-proj -> bf16 (x gate^2 x scale);
// 1 aff+mask -> bf16 logits; 2 att@V -> bf16; 3 relu(acc+bl)+x1 -> fp32.
#define KC 64
#define PLANE_B 16384   // 128 rows * 128 B
#define STAGE_B 32768   // A + B
#define SMEM_BYTES 65536

template <int MODE>
__global__ void __launch_bounds__(256, 2)
mma_gemm(const unsigned short* __restrict__ Ab, int lda, long sAz, long sAh2,
         const unsigned short* __restrict__ Bb, int ldb, long sBz, long sBh2,
         int K,
         float* __restrict__ Cf, unsigned short* __restrict__ Ch,
         int ldc, long sCz, long sCh2,
         const float* __restrict__ e0, const float* __restrict__ e1,
         const unsigned int* __restrict__ maskb) {
    extern __shared__ char smem[];
    uint32_t sbase = smem_u32(smem);
    int tid = threadIdx.x;
    int lid = tid & 31, wid = tid >> 5;
    int wm = wid & 3, wn = wid >> 2;

    int z = blockIdx.z;
    const unsigned short* pA = Ab + (long)(z >> 3) * sAz + (long)(z & 7) * sAh2;
    const unsigned short* pB = Bb + (long)(z >> 3) * sBz + (long)(z & 7) * sBh2;
    long zC = (long)(z >> 3) * sCz + (long)(z & 7) * sCh2;
    const unsigned int* msk = (MODE == 1) ? (maskb + (size_t)(z >> 3) * NN * NN) : nullptr;

    int bm = blockIdx.y * 128;
    int bn = blockIdx.x * 128;

    float acc[2][8][4];
#pragma unroll
    for (int i = 0; i < 2; i++)
#pragma unroll
        for (int j = 0; j < 8; j++)
#pragma unroll
            for (int k = 0; k < 4; k++) acc[i][j][k] = 0.f;

    int rowAl = ((lid >> 3) & 1) * 8 + (lid & 7);
    int aK = lid >> 4;
    int rowBl = ((lid >> 4) & 1) * 8 + (lid & 7);
    int bK = (lid >> 3) & 1;
    uint32_t swz = (uint32_t)(lid & 7);
    uint32_t offA = (uint32_t)(wm * 32 + rowAl) * 128;
    uint32_t offBp[4];
#pragma unroll
    for (int p = 0; p < 4; p++)
        offBp[p] = PLANE_B + (uint32_t)(wn * 64 + p * 16 + rowBl) * 128;

#define LOAD_PLANE(dstoff, src, ld, row0, k0)                                   \
    {                                                                           \
        _Pragma("unroll") for (int t = 0; t < 4; t++) {                         \
            int idx = tid + t * 256;                                            \
            int row = idx >> 3, ch = idx & 7;                                   \
            uint32_t d = (dstoff) + (uint32_t)row * 128 +                       \
                         ((uint32_t)(ch ^ (row & 7)) << 4);                     \
            cpa16(d, (src) + (size_t)((row0) + row) * (ld) + (k0) + ch * 8);    \
        }                                                                       \
    }
#define LOAD_STAGE(st, k0)                                      \
    {                                                           \
        uint32_t sb_ = sbase + (uint32_t)(st) * STAGE_B;        \
        LOAD_PLANE(sb_, pA, lda, bm, k0);                       \
        LOAD_PLANE(sb_ + PLANE_B, pB, ldb, bn, k0);             \
    }

    int nch = K >> 6;
    LOAD_STAGE(0, 0);
    CP_COMMIT();

    for (int c = 0; c < nch; c++) {
        if (c + 1 < nch) {
            LOAD_STAGE((c + 1) & 1, (c + 1) * KC);
            CP_COMMIT();
            CP_WAIT(1);
        } else {
            CP_WAIT(0);
        }
        __syncthreads();

        uint32_t ss = sbase + (uint32_t)(c & 1) * STAGE_B;
#pragma unroll
        for (int s = 0; s < 4; s++) {
            uint32_t a0[4], a1[4], bF[16];
            uint32_t kchA = ((uint32_t)(2 * s + aK) ^ swz) << 4;
            uint32_t kchB = ((uint32_t)(2 * s + bK) ^ swz) << 4;
            ldsm4(a0, ss + offA + kchA);
            ldsm4(a1, ss + offA + 2048 + kchA);
#pragma unroll
            for (int p = 0; p < 4; p++) ldsm4(bF + p * 4, ss + offBp[p] + kchB);
#pragma unroll
            for (int nt = 0; nt < 8; nt++) {
                mma_bf16(acc[0][nt], a0, bF + nt * 2);
                mma_bf16(acc[1][nt], a1, bF + nt * 2);
            }
        }
        __syncthreads();
    }

    // epilogue
    int g = lid >> 2, t = lid & 3;
    const float SCALE = 0.08838834764831845f;  // 1/sqrt(128)
#pragma unroll
    for (int mt = 0; mt < 2; mt++) {
#pragma unroll
        for (int h2 = 0; h2 < 2; h2++) {
            int r = bm + wm * 32 + mt * 16 + g + h2 * 8;
#pragma unroll
            for (int nt = 0; nt < 8; nt++) {
                int c = bn + wn * 64 + nt * 8 + t * 2;
                float v0 = acc[mt][nt][h2 * 2 + 0];
                float v1 = acc[mt][nt][h2 * 2 + 1];
                size_t co = (size_t)zC + (size_t)r * ldc + c;
                if (MODE == 0) {
                    // (acc + bq) * gate^2 * scale   (gate^2 folded onto Q side)
                    int gb = (r >> 9) << 10;
                    float g0 = e1[gb + c], g1 = e1[gb + c + 1];
                    v0 = (v0 + e0[c]) * g0 * g0 * SCALE;
                    v1 = (v1 + e0[c + 1]) * g1 * g1 * SCALE;
                    *reinterpret_cast<uint32_t*>(Ch + co) = pack_bf2(v0, v1);
                } else if (MODE == 1) {
                    uint2 mm = *reinterpret_cast<const uint2*>(msk + (size_t)r * NN + c);
                    v0 = mm.x ? -1e9f : v0;
                    v1 = mm.y ? -1e9f : v1;
                    *reinterpret_cast<uint32_t*>(Ch + co) = pack_bf2(v0, v1);
                } else if (MODE == 2) {
                    *reinterpret_cast<uint32_t*>(Ch + co) = pack_bf2(v0, v1);
                } else {
                    size_t ro = (size_t)r * FF + c;
                    v0 = fmaxf(v0 + e0[c], 0.f) + e1[ro];
                    v1 = fmaxf(v1 + e0[c + 1], 0.f) + e1[ro + 1];
                    *reinterpret_cast<float2*>(Cf + co) = make_float2(v0, v1);
                }
            }
        }
    }
}

// ---------------------------------------------------------------------------
extern "C" void kernel_launch(void* const* d_in, const int* in_sizes, int n_in,
                              void* d_out, int out_size) {
    const float* x1 = (const float*)d_in[0];
    const float* x2 = (const float*)d_in[1];
    const unsigned int* mask = (const unsigned int*)d_in[4];
    const float* Wq = (const float*)d_in[5];
    const float* bq = (const float*)d_in[6];
    const float* Wl = (const float*)d_in[7];
    const float* bl = (const float*)d_in[8];

    float* out_x = (float*)d_out;
    float* out_att = (float*)d_out + ((size_t)out_size - (size_t)BB * HH * NN * NN);

    float *p_gate, *p_gpart;
    unsigned short *x1h, *qgh, *vth, *vbh, *wqth, *wlth, *lgt, *atth;
    cudaGetSymbolAddress((void**)&p_gate, g_gate);
    cudaGetSymbolAddress((void**)&p_gpart, g_gpart);
    cudaGetSymbolAddress((void**)&x1h, g_x1h);
    cudaGetSymbolAddress((void**)&qgh, g_qgh);
    cudaGetSymbolAddress((void**)&vth, g_vth);
    cudaGetSymbolAddress((void**)&vbh, g_vbh);
    cudaGetSymbolAddress((void**)&wqth, g_wqth);
    cudaGetSymbolAddress((void**)&wlth, g_wlth);
    cudaGetSymbolAddress((void**)&lgt, g_lgt);
    cudaGetSymbolAddress((void**)&atth, g_atth);

    // One-time stream/event setup (host-side objects only; no device memory)
    static cudaStream_t s1 = nullptr, s2 = nullptr;
    static cudaEvent_t eFork, eGate, eWq, eVt, eWl, eAff, eS2;
    if (!s1) {
        cudaStreamCreateWithFlags(&s1, cudaStreamNonBlocking);
        cudaStreamCreateWithFlags(&s2, cudaStreamNonBlocking);
        cudaEventCreateWithFlags(&eFork, cudaEventDisableTiming);
        cudaEventCreateWithFlags(&eGate, cudaEventDisableTiming);
        cudaEventCreateWithFlags(&eWq, cudaEventDisableTiming);
        cudaEventCreateWithFlags(&eVt, cudaEventDisableTiming);
        cudaEventCreateWithFlags(&eWl, cudaEventDisableTiming);
        cudaEventCreateWithFlags(&eAff, cudaEventDisableTiming);
        cudaEventCreateWithFlags(&eS2, cudaEventDisableTiming);
        cudaFuncSetAttribute(mma_gemm<0>, cudaFuncAttributeMaxDynamicSharedMemorySize, SMEM_BYTES);
        cudaFuncSetAttribute(mma_gemm<1>, cudaFuncAttributeMaxDynamicSharedMemorySize, SMEM_BYTES);
        cudaFuncSetAttribute(mma_gemm<2>, cudaFuncAttributeMaxDynamicSharedMemorySize, SMEM_BYTES);
        cudaFuncSetAttribute(mma_gemm<3>, cudaFuncAttributeMaxDynamicSharedMemorySize, SMEM_BYTES);
    }

    // Fork side stream s1 off the main stream
    cudaEventRecord(eFork, 0);
    cudaStreamWaitEvent(s1, eFork, 0);

    // s1: gate chain + weight/V conversions (off critical path)
    gate_part<<<dim3(8, BB), 1024, 0, s1>>>(x2, p_gpart);
    gate_reduce<<<BB, 1024, 0, s1>>>(p_gpart, p_gate);
    conv_wq<<<dim3(FF / 32, DD / 32, HH), dim3(32, 8), 0, s1>>>(Wq, wqth);
    cudaEventRecord(eWq, s1);  // gate + wqt ready
    conv_vt<<<dim3(NN / 32, DD / 32, BB * HH), dim3(32, 8), 0, s1>>>(x1, vth);
    cudaEventRecord(eVt, s1);
    conv_wl<<<dim3(FF / 32, FF / 32), dim3(32, 8), 0, s1>>>(Wl, wlth);
    cudaEventRecord(eWl, s1);

    // s0 (main/critical path)
    conv_x1<<<(BB * NN * FF) / 1024, 256>>>((const float4*)x1, (uint2*)x1h);
    cudaStreamWaitEvent(0, eWq, 0);
    // Qg = (x1 @ Wqt + bq) * gate^2 * scale -> bf16   [16384x1024x1024]
    mma_gemm<0><<<dim3(8, 128, 1), 256, SMEM_BYTES>>>(
        x1h, 1024, 0, 0, wqth, 1024, 0, 0, 1024,
        nullptr, qgh, 1024, 0, 0, bq, p_gate, nullptr);
    // aff = Qg2 @ x1^T, mask fused -> bf16 logits   [512x512x128] x 256
    mma_gemm<1><<<dim3(4, 4, 256), 256, SMEM_BYTES>>>(
        qgh, 1024, (long)NN * FF, DD, x1h, 1024, (long)NN * FF, DD, 128,
        nullptr, lgt, 512, 8L * NN * NN, (long)NN * NN,
        nullptr, nullptr, mask);
    cudaEventRecord(eAff, 0);

    // s2: fp32 att output (overlaps att@V + final GEMM)
    cudaStreamWaitEvent(s2, eAff, 0);
    softmax_f32<<<(BB * HH * NN) / 8, 256, 0, s2>>>(lgt, out_att);
    cudaEventRecord(eS2, s2);

    // s0: bf16 softmax -> att@V -> final
    softmax_bf16<<<(BB * HH * NN) / 8, 256>>>(lgt, atth);
    cudaStreamWaitEvent(0, eVt, 0);
    // vb = att @ V -> bf16   [512x128x512] x 256
    mma_gemm<2><<<dim3(1, 4, 256), 256, SMEM_BYTES>>>(
        atth, 512, 8L * NN * NN, (long)NN * NN, vth, 512, 8L * DD * NN, (long)DD * NN, 512,
        nullptr, vbh, 1024, (long)NN * FF, DD,
        nullptr, nullptr, nullptr);
    cudaStreamWaitEvent(0, eWl, 0);
    // xout = relu(vb @ Wlt + bl) + x1   [16384x1024x1024]
    mma_gemm<3><<<dim3(8, 128, 1), 256, SMEM_BYTES>>>(
        vbh, 1024, 0, 0, wlth, 1024, 0, 0, 1024,
        out_x, nullptr, 1024, 0, 0, bl, x1, nullptr);
    // join s2 (fp32 att write) back into the main stream
    cudaStreamWaitEvent(0, eS2, 0);
}